// round 1
// baseline (speedup 1.0000x reference)
#include <cuda_runtime.h>

#define TLEN 2048
#define HEADS 8
#define HDIM 32
#define BSZ 4
#define NEMB 256

// Scratch (static __device__ arrays: allocation-free)
__device__ float g_Q[(size_t)BSZ*HEADS*TLEN*HDIM];
__device__ float g_K[(size_t)BSZ*HEADS*TLEN*HDIM];
__device__ float g_V[(size_t)BSZ*HEADS*TLEN*HDIM];
__device__ float g_O[(size_t)BSZ*TLEN*NEMB];

// ---------------------------------------------------------------------------
// Kernel 1: qkv = x @ w_attn, split K|Q|V (in that order!), reshape to heads,
// fold 1/sqrt(32) into Q.  M=8192, K=256, N=768. 64x64 tile, 256 threads.
// ---------------------------------------------------------------------------
__global__ void qkv_kernel(const float* __restrict__ x, const float* __restrict__ w) {
    __shared__ float As[64][20];
    __shared__ float Bs[16][68];
    int tid = threadIdx.x;
    int tx = tid & 15, ty = tid >> 4;
    int m0 = blockIdx.y * 64, n0 = blockIdx.x * 64;

    float acc[4][4] = {};

    for (int kk = 0; kk < 256; kk += 16) {
        {   // A tile: 64x16 of x
            int row = tid >> 2, c4 = (tid & 3) * 4;
            float4 v = *(const float4*)&x[(size_t)(m0 + row) * 256 + kk + c4];
            As[row][c4] = v.x; As[row][c4+1] = v.y; As[row][c4+2] = v.z; As[row][c4+3] = v.w;
        }
        {   // B tile: 16x64 of w_attn [256][768]
            int r = tid >> 4, c4 = (tid & 15) * 4;
            float4 v = *(const float4*)&w[(size_t)(kk + r) * 768 + n0 + c4];
            Bs[r][c4] = v.x; Bs[r][c4+1] = v.y; Bs[r][c4+2] = v.z; Bs[r][c4+3] = v.w;
        }
        __syncthreads();
#pragma unroll
        for (int k = 0; k < 16; k++) {
            float4 bv = *(const float4*)&Bs[k][tx * 4];
            float a0 = As[ty*4+0][k], a1 = As[ty*4+1][k], a2 = As[ty*4+2][k], a3 = As[ty*4+3][k];
            acc[0][0] += a0*bv.x; acc[0][1] += a0*bv.y; acc[0][2] += a0*bv.z; acc[0][3] += a0*bv.w;
            acc[1][0] += a1*bv.x; acc[1][1] += a1*bv.y; acc[1][2] += a1*bv.z; acc[1][3] += a1*bv.w;
            acc[2][0] += a2*bv.x; acc[2][1] += a2*bv.y; acc[2][2] += a2*bv.z; acc[2][3] += a2*bv.w;
            acc[3][0] += a3*bv.x; acc[3][1] += a3*bv.y; acc[3][2] += a3*bv.z; acc[3][3] += a3*bv.w;
        }
        __syncthreads();
    }

    // route to K/Q/V with [B,H,T,D] layout
    int c_base = n0 + tx * 4;            // all 4 cols share part/head
    int part = c_base >> 8;              // 0=K, 1=Q, 2=V  (jnp.split order!)
    int cc = c_base & 255;
    int h = cc >> 5, d = cc & 31;
    float scale = (part == 1) ? 0.17677669529663687f : 1.0f;  // 1/sqrt(32) on Q
    float* dst = (part == 0) ? g_K : (part == 1) ? g_Q : g_V;
#pragma unroll
    for (int i = 0; i < 4; i++) {
        int m = m0 + ty * 4 + i;
        int b = m >> 11, t = m & 2047;
        float* p = &dst[(((size_t)(b * HEADS + h)) * TLEN + t) * HDIM + d];
#pragma unroll
        for (int j = 0; j < 4; j++) p[j] = acc[i][j] * scale;
    }
}

// ---------------------------------------------------------------------------
// Kernel 2: fused flash attention with relative-position band.
// S[t,s] = Q[t]·K[s] + Q[t]·pe[T-1-(t-s)]   (Q pre-scaled), causal mask,
// online softmax, O += P·V.  BQ=BK=64, D=32, 256 threads.
// pe rows needed per key tile form a band of 127 rows starting at
// gbase = T-64-t0+s0; local index j' = j - i + 63.
// ---------------------------------------------------------------------------
__global__ void attn_kernel(const float* __restrict__ pos) {
    extern __shared__ float sm[];
    float* Qs  = sm;                 // [64][33]
    float* Ks  = Qs  + 64 * 33;      // [64][33]
    float* Pes = Ks  + 64 * 33;      // [128][33] (127 used)
    float* Vs  = Pes + 128 * 33;     // [64][32]
    float* Ss  = Vs  + 64 * 32;      // [64][65]

    int tid = threadIdx.x;
    int h = blockIdx.y, b = blockIdx.z;
    int t0 = (gridDim.x - 1 - blockIdx.x) * 64;   // big tiles launch first

    const float* Qg  = &g_Q[(((size_t)(b * HEADS + h)) * TLEN + t0) * HDIM];
    const float* Kb  = &g_K[((size_t)(b * HEADS + h)) * TLEN * HDIM];
    const float* Vb  = &g_V[((size_t)(b * HEADS + h)) * TLEN * HDIM];
    const float* peh = &pos[(size_t)h * TLEN * HDIM];

    // load Q tile once
    for (int e = tid; e < 64 * 32; e += 256)
        Qs[(e >> 5) * 33 + (e & 31)] = Qg[e];

    // per-thread flash state: row rowi, cols d0..d0+7
    int rowi = tid >> 2;
    int d0 = (tid & 3) * 8;
    float acc[8] = {0,0,0,0,0,0,0,0};
    float m_i = -1e30f, l_i = 0.0f;

    int tx = tid & 15, ty = tid >> 4;
    int i0 = ty * 4, j0 = tx * 4;

    int nIter = t0 / 64 + 1;
    for (int it = 0; it < nIter; it++) {
        int s0 = it * 64;
        __syncthreads();   // protect Ss/Ks/Vs/Pes reuse from previous iter

        for (int e = tid; e < 64 * 32; e += 256) {
            Ks[(e >> 5) * 33 + (e & 31)] = Kb[(size_t)s0 * 32 + e];
            Vs[e] = Vb[(size_t)s0 * 32 + e];
        }
        int gbase = (TLEN - 64) - t0 + s0;   // >= 0 always
        for (int e = tid; e < 127 * 32; e += 256) {
            int r = e >> 5, d = e & 31;
            int gr = gbase + r;
            if (gr > TLEN - 1) gr = TLEN - 1;  // OOB rows are causally masked anyway
            Pes[r * 33 + d] = peh[(size_t)gr * 32 + d];
        }
        __syncthreads();

        // --- scores: 4x4 micro-tile per thread ---
        float s[4][4] = {};
        int jb = j0 - i0 + 63;               // pe band base for (di=dj)
#pragma unroll 8
        for (int d = 0; d < 32; d++) {
            float k0 = Ks[(j0+0)*33 + d], k1 = Ks[(j0+1)*33 + d];
            float k2 = Ks[(j0+2)*33 + d], k3 = Ks[(j0+3)*33 + d];
            float p[7];
#pragma unroll
            for (int o = 0; o < 7; o++) p[o] = Pes[(jb + o - 3) * 33 + d];
#pragma unroll
            for (int di = 0; di < 4; di++) {
                float q = Qs[(i0 + di) * 33 + d];
                s[di][0] += q * (k0 + p[3 - di]);
                s[di][1] += q * (k1 + p[4 - di]);
                s[di][2] += q * (k2 + p[5 - di]);
                s[di][3] += q * (k3 + p[6 - di]);
            }
        }
        // causal mask + stage to smem
#pragma unroll
        for (int di = 0; di < 4; di++) {
            int tt = t0 + i0 + di;
#pragma unroll
            for (int dj = 0; dj < 4; dj++) {
                int ss = s0 + j0 + dj;
                Ss[(i0 + di) * 65 + (j0 + dj)] = (ss <= tt) ? s[di][dj] : -1e30f;
            }
        }
        __syncthreads();

        // --- online softmax: quad of 4 threads per row ---
        {
            int jseg = (tid & 3) * 16;
            float mloc = -1e30f;
#pragma unroll
            for (int j = 0; j < 16; j++) mloc = fmaxf(mloc, Ss[rowi * 65 + jseg + j]);
            mloc = fmaxf(mloc, __shfl_xor_sync(0xffffffffu, mloc, 1));
            mloc = fmaxf(mloc, __shfl_xor_sync(0xffffffffu, mloc, 2));
            float m_new = fmaxf(m_i, mloc);
            float ssum = 0.0f;
#pragma unroll
            for (int j = 0; j < 16; j++) {
                float e = __expf(Ss[rowi * 65 + jseg + j] - m_new);
                Ss[rowi * 65 + jseg + j] = e;
                ssum += e;
            }
            ssum += __shfl_xor_sync(0xffffffffu, ssum, 1);
            ssum += __shfl_xor_sync(0xffffffffu, ssum, 2);
            float corr = __expf(m_i - m_new);
            l_i = l_i * corr + ssum;
            m_i = m_new;
#pragma unroll
            for (int k = 0; k < 8; k++) acc[k] *= corr;
        }
        __syncwarp();   // row's P written by its own quad (same warp)

        // --- P @ V ---
#pragma unroll 4
        for (int j = 0; j < 64; j++) {
            float p = Ss[rowi * 65 + j];
            const float4* v4 = (const float4*)&Vs[j * 32 + d0];
            float4 v0 = v4[0], v1 = v4[1];
            acc[0] += p * v0.x; acc[1] += p * v0.y; acc[2] += p * v0.z; acc[3] += p * v0.w;
            acc[4] += p * v1.x; acc[5] += p * v1.y; acc[6] += p * v1.z; acc[7] += p * v1.w;
        }
    }

    // write O in [B, T, H*D] layout (= transpose+reshape in reference)
    float inv = 1.0f / l_i;
    float* op = &g_O[((size_t)b * TLEN + t0 + rowi) * NEMB + h * HDIM + d0];
#pragma unroll
    for (int k = 0; k < 8; k++) op[k] = acc[k] * inv;
}

// ---------------------------------------------------------------------------
// Kernel 3: out = O @ w_proj + b_proj.  M=8192, K=256, N=256.
// ---------------------------------------------------------------------------
__global__ void proj_kernel(const float* __restrict__ w, const float* __restrict__ bias,
                            float* __restrict__ out) {
    __shared__ float As[64][20];
    __shared__ float Bs[16][68];
    int tid = threadIdx.x;
    int tx = tid & 15, ty = tid >> 4;
    int m0 = blockIdx.y * 64, n0 = blockIdx.x * 64;

    float acc[4][4] = {};

    for (int kk = 0; kk < 256; kk += 16) {
        {
            int row = tid >> 2, c4 = (tid & 3) * 4;
            float4 v = *(const float4*)&g_O[(size_t)(m0 + row) * 256 + kk + c4];
            As[row][c4] = v.x; As[row][c4+1] = v.y; As[row][c4+2] = v.z; As[row][c4+3] = v.w;
        }
        {
            int r = tid >> 4, c4 = (tid & 15) * 4;
            float4 v = *(const float4*)&w[(size_t)(kk + r) * 256 + n0 + c4];
            Bs[r][c4] = v.x; Bs[r][c4+1] = v.y; Bs[r][c4+2] = v.z; Bs[r][c4+3] = v.w;
        }
        __syncthreads();
#pragma unroll
        for (int k = 0; k < 16; k++) {
            float4 bv = *(const float4*)&Bs[k][tx * 4];
            float a0 = As[ty*4+0][k], a1 = As[ty*4+1][k], a2 = As[ty*4+2][k], a3 = As[ty*4+3][k];
            acc[0][0] += a0*bv.x; acc[0][1] += a0*bv.y; acc[0][2] += a0*bv.z; acc[0][3] += a0*bv.w;
            acc[1][0] += a1*bv.x; acc[1][1] += a1*bv.y; acc[1][2] += a1*bv.z; acc[1][3] += a1*bv.w;
            acc[2][0] += a2*bv.x; acc[2][1] += a2*bv.y; acc[2][2] += a2*bv.z; acc[2][3] += a2*bv.w;
            acc[3][0] += a3*bv.x; acc[3][1] += a3*bv.y; acc[3][2] += a3*bv.z; acc[3][3] += a3*bv.w;
        }
        __syncthreads();
    }

    int n = n0 + tx * 4;
    float b0 = bias[n], b1 = bias[n+1], b2 = bias[n+2], b3 = bias[n+3];
#pragma unroll
    for (int i = 0; i < 4; i++) {
        int m = m0 + ty * 4 + i;
        float* p = &out[(size_t)m * 256 + n];
        p[0] = acc[i][0] + b0; p[1] = acc[i][1] + b1;
        p[2] = acc[i][2] + b2; p[3] = acc[i][3] + b3;
    }
}

// ---------------------------------------------------------------------------
extern "C" void kernel_launch(void* const* d_in, const int* in_sizes, int n_in,
                              void* d_out, int out_size) {
    const float* x      = (const float*)d_in[0];
    const float* w_attn = (const float*)d_in[1];
    const float* pos    = (const float*)d_in[2];
    const float* w_proj = (const float*)d_in[3];
    const float* b_proj = (const float*)d_in[4];
    float* out = (float*)d_out;

    // QKV GEMM: M=8192 (rows of x), N=768
    qkv_kernel<<<dim3(12, 128), 256>>>(x, w_attn);

    // Attention: (T/64, H, B)
    const size_t attn_smem = (64*33 + 64*33 + 128*33 + 64*32 + 64*65) * sizeof(float); // 58624 B
    static int attr_set = 0;
    if (!attr_set) {
        cudaFuncSetAttribute(attn_kernel, cudaFuncAttributeMaxDynamicSharedMemorySize,
                             (int)attn_smem);
        attr_set = 1;
    }
    attn_kernel<<<dim3(32, 8, 4), 256, attn_smem>>>(pos);

    // Output projection: M=8192, N=256
    proj_kernel<<<dim3(4, 128), 256>>>(w_proj, b_proj, out);
}

// round 2
// speedup vs baseline: 1.6790x; 1.6790x over previous
#include <cuda_runtime.h>
#include <cstdint>

#define TLEN 2048
#define HEADS 8
#define HDIM 32
#define BSZ 4
#define NEMB 256

__device__ float g_Q[(size_t)BSZ*HEADS*TLEN*HDIM];
__device__ float g_K[(size_t)BSZ*HEADS*TLEN*HDIM];
__device__ float g_V[(size_t)BSZ*HEADS*TLEN*HDIM];
__device__ float g_O[(size_t)BSZ*TLEN*NEMB];

// ---------------------------------------------------------------------------
__device__ __forceinline__ uint32_t f2tf(float x) {
    uint32_t r;
    asm("cvt.rna.tf32.f32 %0, %1;" : "=r"(r) : "f"(x));
    return r;
}

__device__ __forceinline__ void mma_tf32(float c[4],
                                         uint32_t a0, uint32_t a1, uint32_t a2, uint32_t a3,
                                         uint32_t b0, uint32_t b1) {
    asm volatile(
        "mma.sync.aligned.m16n8k8.row.col.f32.tf32.tf32.f32 "
        "{%0,%1,%2,%3}, {%4,%5,%6,%7}, {%8,%9}, {%0,%1,%2,%3};\n"
        : "+f"(c[0]), "+f"(c[1]), "+f"(c[2]), "+f"(c[3])
        : "r"(a0), "r"(a1), "r"(a2), "r"(a3), "r"(b0), "r"(b1));
}

// ---------------------------------------------------------------------------
// Kernel 1: qkv = x @ w_attn, split K|Q|V, heads layout, fold 1/sqrt(32) in Q.
// ---------------------------------------------------------------------------
__global__ void qkv_kernel(const float* __restrict__ x, const float* __restrict__ w) {
    __shared__ float As[64][20];
    __shared__ float Bs[16][68];
    int tid = threadIdx.x;
    int tx = tid & 15, ty = tid >> 4;
    int m0 = blockIdx.y * 64, n0 = blockIdx.x * 64;

    float acc[4][4] = {};

    for (int kk = 0; kk < 256; kk += 16) {
        {
            int row = tid >> 2, c4 = (tid & 3) * 4;
            float4 v = *(const float4*)&x[(size_t)(m0 + row) * 256 + kk + c4];
            As[row][c4] = v.x; As[row][c4+1] = v.y; As[row][c4+2] = v.z; As[row][c4+3] = v.w;
        }
        {
            int r = tid >> 4, c4 = (tid & 15) * 4;
            float4 v = *(const float4*)&w[(size_t)(kk + r) * 768 + n0 + c4];
            Bs[r][c4] = v.x; Bs[r][c4+1] = v.y; Bs[r][c4+2] = v.z; Bs[r][c4+3] = v.w;
        }
        __syncthreads();
#pragma unroll
        for (int k = 0; k < 16; k++) {
            float4 bv = *(const float4*)&Bs[k][tx * 4];
            float a0 = As[ty*4+0][k], a1 = As[ty*4+1][k], a2 = As[ty*4+2][k], a3 = As[ty*4+3][k];
            acc[0][0] += a0*bv.x; acc[0][1] += a0*bv.y; acc[0][2] += a0*bv.z; acc[0][3] += a0*bv.w;
            acc[1][0] += a1*bv.x; acc[1][1] += a1*bv.y; acc[1][2] += a1*bv.z; acc[1][3] += a1*bv.w;
            acc[2][0] += a2*bv.x; acc[2][1] += a2*bv.y; acc[2][2] += a2*bv.z; acc[2][3] += a2*bv.w;
            acc[3][0] += a3*bv.x; acc[3][1] += a3*bv.y; acc[3][2] += a3*bv.z; acc[3][3] += a3*bv.w;
        }
        __syncthreads();
    }

    int c_base = n0 + tx * 4;
    int part = c_base >> 8;              // 0=K, 1=Q, 2=V
    int cc = c_base & 255;
    int h = cc >> 5, d = cc & 31;
    float scale = (part == 1) ? 0.17677669529663687f : 1.0f;
    float* dst = (part == 0) ? g_K : (part == 1) ? g_Q : g_V;
#pragma unroll
    for (int i = 0; i < 4; i++) {
        int m = m0 + ty * 4 + i;
        int b = m >> 11, t = m & 2047;
        float* p = &dst[(((size_t)(b * HEADS + h)) * TLEN + t) * HDIM + d];
#pragma unroll
        for (int j = 0; j < 4; j++) p[j] = acc[i][j] * scale;
    }
}

// ---------------------------------------------------------------------------
// Kernel 2: flash attention, tf32 mma.sync for QK / Q-pe band / PV.
// BQ=64, BK=128, 8 warps. Band: S[i,j] += R[i, j-i+63],
// R = Q · pe_band^T, pe band rows = gbase..gbase+190, gbase = 1984 - t0 + s0.
// ---------------------------------------------------------------------------
__global__ void attn_kernel(const float* __restrict__ pos) {
    extern __shared__ float sm[];
    float* Qs   = sm;                  // [64][36]
    float* Ks   = Qs  + 64 * 36;       // [128][36]
    float* Pes  = Ks  + 128 * 36;      // [192][36]
    float* Vs   = Pes + 192 * 36;      // [128][36]
    float* Ss   = Vs  + 128 * 36;      // [64][133]
    float* corr = Ss  + 64 * 133;      // [64]
    float* lsum = corr + 64;           // [64]

    int tid = threadIdx.x;
    int lane = tid & 31, wid = tid >> 5;
    int g = lane >> 2, t4 = lane & 3;
    int h = blockIdx.y, b = blockIdx.z;
    int t0 = (gridDim.x - 1 - blockIdx.x) * 64;

    const float* Qg  = &g_Q[(((size_t)(b * HEADS + h)) * TLEN + t0) * HDIM];
    const float* Kb  = &g_K[((size_t)(b * HEADS + h)) * TLEN * HDIM];
    const float* Vb  = &g_V[((size_t)(b * HEADS + h)) * TLEN * HDIM];
    const float* peh = &pos[(size_t)h * TLEN * HDIM];

    // load Q tile
    for (int e = tid; e < 64 * 32; e += 256)
        Qs[(e >> 5) * 36 + (e & 31)] = Qg[e];

    int mt = wid >> 1, nh = wid & 1;
    int arow0 = mt * 16 + g;           // MMA A-frag base row
    int srow = tid >> 2, seg = tid & 3;  // softmax ownership

    float o0[4] = {0,0,0,0}, o1[4] = {0,0,0,0};
    float m_i = -1e30f, l_i = 0.0f;

    int nK = (t0 + 191) >> 7;
    for (int kt = 0; kt < nK; kt++) {
        int s0 = kt << 7;
        __syncthreads();

        for (int e = tid; e < 128 * 32; e += 256) {
            int r = e >> 5, c = e & 31;
            Ks[r * 36 + c] = Kb[(size_t)s0 * 32 + e];
            Vs[r * 36 + c] = Vb[(size_t)s0 * 32 + e];
        }
        int gbase = 1984 - t0 + s0;    // >= 0 always
        for (int e = tid; e < 192 * 32; e += 256) {
            int r = e >> 5, c = e & 31;
            int gr = gbase + r; if (gr > 2047) gr = 2047;
            Pes[r * 36 + c] = peh[(size_t)gr * 32 + c];
        }
        __syncthreads();

        // ---- QK GEMM: S[64,128] = Q·K^T, warp covers mt x (nh*8..+7) ----
        {
            float c8[8][4] = {};
#pragma unroll
            for (int ks = 0; ks < 4; ks++) {
                uint32_t a0 = f2tf(Qs[arow0 * 36 + ks*8 + t4]);
                uint32_t a1 = f2tf(Qs[(arow0+8) * 36 + ks*8 + t4]);
                uint32_t a2 = f2tf(Qs[arow0 * 36 + ks*8 + t4 + 4]);
                uint32_t a3 = f2tf(Qs[(arow0+8) * 36 + ks*8 + t4 + 4]);
#pragma unroll
                for (int nn = 0; nn < 8; nn++) {
                    int nt = nh * 8 + nn;
                    uint32_t b0 = f2tf(Ks[(nt*8+g) * 36 + ks*8 + t4]);
                    uint32_t b1 = f2tf(Ks[(nt*8+g) * 36 + ks*8 + t4 + 4]);
                    mma_tf32(c8[nn], a0, a1, a2, a3, b0, b1);
                }
            }
#pragma unroll
            for (int nn = 0; nn < 8; nn++) {
                int col = (nh*8+nn) * 8 + 2*t4;
                Ss[arow0 * 133 + col]       = c8[nn][0];
                Ss[arow0 * 133 + col + 1]   = c8[nn][1];
                Ss[(arow0+8) * 133 + col]   = c8[nn][2];
                Ss[(arow0+8) * 133 + col+1] = c8[nn][3];
            }
        }
        __syncthreads();

        // ---- band GEMM R[64,191] = Q·pe^T, scatter-add into Ss ----
#pragma unroll
        for (int chunk = 0; chunk < 2; chunk++) {
            float cr[6][4] = {};
#pragma unroll
            for (int ks = 0; ks < 4; ks++) {
                uint32_t a0 = f2tf(Qs[arow0 * 36 + ks*8 + t4]);
                uint32_t a1 = f2tf(Qs[(arow0+8) * 36 + ks*8 + t4]);
                uint32_t a2 = f2tf(Qs[arow0 * 36 + ks*8 + t4 + 4]);
                uint32_t a3 = f2tf(Qs[(arow0+8) * 36 + ks*8 + t4 + 4]);
#pragma unroll
                for (int uu = 0; uu < 6; uu++) {
                    int ut = nh * 12 + chunk * 6 + uu;
                    uint32_t b0 = f2tf(Pes[(ut*8+g) * 36 + ks*8 + t4]);
                    uint32_t b1 = f2tf(Pes[(ut*8+g) * 36 + ks*8 + t4 + 4]);
                    mma_tf32(cr[uu], a0, a1, a2, a3, b0, b1);
                }
            }
#pragma unroll
            for (int uu = 0; uu < 6; uu++) {
                int ut = nh * 12 + chunk * 6 + uu;
                int u0 = ut * 8 + 2*t4;
                int j0 = u0 + arow0 - 63;      // row arow0
                if (j0 >= 0 && j0 < 128)      Ss[arow0 * 133 + j0]     += cr[uu][0];
                if (j0+1 >= 0 && j0+1 < 128)  Ss[arow0 * 133 + j0 + 1] += cr[uu][1];
                int j1 = u0 + arow0 + 8 - 63;  // row arow0+8
                if (j1 >= 0 && j1 < 128)      Ss[(arow0+8) * 133 + j1]     += cr[uu][2];
                if (j1+1 >= 0 && j1+1 < 128)  Ss[(arow0+8) * 133 + j1 + 1] += cr[uu][3];
            }
        }
        __syncthreads();

        // ---- online softmax (quad per row) ----
        {
            int rb = srow * 133;
            int tmax = t0 + srow - s0;   // valid col j <= tmax
            float mloc = -1e30f;
#pragma unroll
            for (int jj = 0; jj < 32; jj++) {
                int col = seg * 32 + ((jj + seg * 8) & 31);
                float v = Ss[rb + col];
                mloc = fmaxf(mloc, (col <= tmax) ? v : -1e30f);
            }
            mloc = fmaxf(mloc, __shfl_xor_sync(0xffffffffu, mloc, 1));
            mloc = fmaxf(mloc, __shfl_xor_sync(0xffffffffu, mloc, 2));
            float m_new = fmaxf(m_i, mloc);
            float cf = __expf(m_i - m_new);
            float ssum = 0.0f;
#pragma unroll
            for (int jj = 0; jj < 32; jj++) {
                int col = seg * 32 + ((jj + seg * 8) & 31);
                float v = Ss[rb + col];
                float e = (col <= tmax) ? __expf(v - m_new) : 0.0f;
                Ss[rb + col] = e;
                ssum += e;
            }
            ssum += __shfl_xor_sync(0xffffffffu, ssum, 1);
            ssum += __shfl_xor_sync(0xffffffffu, ssum, 2);
            l_i = l_i * cf + ssum;
            m_i = m_new;
            if (seg == 0) { corr[srow] = cf; lsum[srow] = l_i; }
        }
        __syncthreads();

        // ---- PV GEMM: O[64,32] += P·V, O frags register-resident ----
        {
            float cf0 = corr[arow0], cf1 = corr[arow0 + 8];
            o0[0] *= cf0; o0[1] *= cf0; o0[2] *= cf1; o0[3] *= cf1;
            o1[0] *= cf0; o1[1] *= cf0; o1[2] *= cf1; o1[3] *= cf1;
            int nt0 = nh * 2, nt1 = nh * 2 + 1;
#pragma unroll
            for (int ks = 0; ks < 16; ks++) {
                uint32_t a0 = f2tf(Ss[arow0 * 133 + ks*8 + t4]);
                uint32_t a1 = f2tf(Ss[(arow0+8) * 133 + ks*8 + t4]);
                uint32_t a2 = f2tf(Ss[arow0 * 133 + ks*8 + t4 + 4]);
                uint32_t a3 = f2tf(Ss[(arow0+8) * 133 + ks*8 + t4 + 4]);
                uint32_t b0 = f2tf(Vs[(ks*8+t4) * 36 + nt0*8 + g]);
                uint32_t b1 = f2tf(Vs[(ks*8+t4+4) * 36 + nt0*8 + g]);
                mma_tf32(o0, a0, a1, a2, a3, b0, b1);
                b0 = f2tf(Vs[(ks*8+t4) * 36 + nt1*8 + g]);
                b1 = f2tf(Vs[(ks*8+t4+4) * 36 + nt1*8 + g]);
                mma_tf32(o1, a0, a1, a2, a3, b0, b1);
            }
        }
    }

    // ---- epilogue: divide by l, write O in [B,T,H*D] ----
    float inv0 = 1.0f / lsum[arow0];
    float inv1 = 1.0f / lsum[arow0 + 8];
    {
        int nt0 = nh * 2, nt1 = nh * 2 + 1;
        int col0 = nt0 * 8 + 2*t4, col1 = nt1 * 8 + 2*t4;
        float* p0 = &g_O[((size_t)b * TLEN + t0 + arow0) * NEMB + h * HDIM];
        float* p1 = &g_O[((size_t)b * TLEN + t0 + arow0 + 8) * NEMB + h * HDIM];
        p0[col0]     = o0[0] * inv0;  p0[col0 + 1] = o0[1] * inv0;
        p1[col0]     = o0[2] * inv1;  p1[col0 + 1] = o0[3] * inv1;
        p0[col1]     = o1[0] * inv0;  p0[col1 + 1] = o1[1] * inv0;
        p1[col1]     = o1[2] * inv1;  p1[col1 + 1] = o1[3] * inv1;
    }
}

// ---------------------------------------------------------------------------
// Kernel 3: out = O @ w_proj + b_proj.
// ---------------------------------------------------------------------------
__global__ void proj_kernel(const float* __restrict__ w, const float* __restrict__ bias,
                            float* __restrict__ out) {
    __shared__ float As[64][20];
    __shared__ float Bs[16][68];
    int tid = threadIdx.x;
    int tx = tid & 15, ty = tid >> 4;
    int m0 = blockIdx.y * 64, n0 = blockIdx.x * 64;

    float acc[4][4] = {};

    for (int kk = 0; kk < 256; kk += 16) {
        {
            int row = tid >> 2, c4 = (tid & 3) * 4;
            float4 v = *(const float4*)&g_O[(size_t)(m0 + row) * 256 + kk + c4];
            As[row][c4] = v.x; As[row][c4+1] = v.y; As[row][c4+2] = v.z; As[row][c4+3] = v.w;
        }
        {
            int r = tid >> 4, c4 = (tid & 15) * 4;
            float4 v = *(const float4*)&w[(size_t)(kk + r) * 256 + n0 + c4];
            Bs[r][c4] = v.x; Bs[r][c4+1] = v.y; Bs[r][c4+2] = v.z; Bs[r][c4+3] = v.w;
        }
        __syncthreads();
#pragma unroll
        for (int k = 0; k < 16; k++) {
            float4 bv = *(const float4*)&Bs[k][tx * 4];
            float a0 = As[ty*4+0][k], a1 = As[ty*4+1][k], a2 = As[ty*4+2][k], a3 = As[ty*4+3][k];
            acc[0][0] += a0*bv.x; acc[0][1] += a0*bv.y; acc[0][2] += a0*bv.z; acc[0][3] += a0*bv.w;
            acc[1][0] += a1*bv.x; acc[1][1] += a1*bv.y; acc[1][2] += a1*bv.z; acc[1][3] += a1*bv.w;
            acc[2][0] += a2*bv.x; acc[2][1] += a2*bv.y; acc[2][2] += a2*bv.z; acc[2][3] += a2*bv.w;
            acc[3][0] += a3*bv.x; acc[3][1] += a3*bv.y; acc[3][2] += a3*bv.z; acc[3][3] += a3*bv.w;
        }
        __syncthreads();
    }

    int n = n0 + tx * 4;
    float b0 = bias[n], b1 = bias[n+1], b2 = bias[n+2], b3 = bias[n+3];
#pragma unroll
    for (int i = 0; i < 4; i++) {
        int m = m0 + ty * 4 + i;
        float* p = &out[(size_t)m * 256 + n];
        p[0] = acc[i][0] + b0; p[1] = acc[i][1] + b1;
        p[2] = acc[i][2] + b2; p[3] = acc[i][3] + b3;
    }
}

// ---------------------------------------------------------------------------
extern "C" void kernel_launch(void* const* d_in, const int* in_sizes, int n_in,
                              void* d_out, int out_size) {
    const float* x      = (const float*)d_in[0];
    const float* w_attn = (const float*)d_in[1];
    const float* pos    = (const float*)d_in[2];
    const float* w_proj = (const float*)d_in[3];
    const float* b_proj = (const float*)d_in[4];
    float* out = (float*)d_out;

    qkv_kernel<<<dim3(12, 128), 256>>>(x, w_attn);

    const size_t attn_smem = (64*36 + 128*36 + 192*36 + 128*36 + 64*133 + 128) * sizeof(float);
    static int attr_set = 0;
    if (!attr_set) {
        cudaFuncSetAttribute(attn_kernel, cudaFuncAttributeMaxDynamicSharedMemorySize,
                             (int)attn_smem);
        attr_set = 1;
    }
    attn_kernel<<<dim3(32, 8, 4), 256, attn_smem>>>(pos);

    proj_kernel<<<dim3(4, 128), 256>>>(w_proj, b_proj, out);
}